// round 2
// baseline (speedup 1.0000x reference)
#include <cuda_runtime.h>

// LIF scan: X[B,C,H,W,T=16] fp32 -> spikes same shape.
// mem = mem*0.5 + x_t; s = (mem >= 1); mem = s ? 0 : mem
// 2 neurons per thread (128 B contiguous), streaming ld/st to keep L2 clean.

#define DECAY 0.5f
#define THRESH 1.0f
#define T_STEPS 16

__device__ __forceinline__ float4 ldcs4(const float4* p) {
    float4 v;
    asm volatile("ld.global.cs.v4.f32 {%0,%1,%2,%3}, [%4];"
                 : "=f"(v.x), "=f"(v.y), "=f"(v.z), "=f"(v.w) : "l"(p));
    return v;
}
__device__ __forceinline__ void stcs4(float4* p, float4 v) {
    asm volatile("st.global.cs.v4.f32 [%0], {%1,%2,%3,%4};"
                 :: "l"(p), "f"(v.x), "f"(v.y), "f"(v.z), "f"(v.w) : "memory");
}

__device__ __forceinline__ void lif16(float* f) {
    float mem = 0.0f;
#pragma unroll
    for (int i = 0; i < T_STEPS; i++) {
        mem = fmaf(mem, DECAY, f[i]);
        bool fire = (mem >= THRESH);
        f[i] = fire ? 1.0f : 0.0f;
        mem  = fire ? 0.0f : mem;
    }
}

__global__ void __launch_bounds__(256)
lif_kernel(const float4* __restrict__ x4, float4* __restrict__ o4, int n_pairs) {
    int t = blockIdx.x * blockDim.x + threadIdx.x;
    if (t >= n_pairs) return;

    // 2 neurons = 32 floats = 8 x float4, contiguous. MLP=8.
    const float4* src = x4 + (size_t)t * 8;
    float4 v0 = ldcs4(src + 0);
    float4 v1 = ldcs4(src + 1);
    float4 v2 = ldcs4(src + 2);
    float4 v3 = ldcs4(src + 3);
    float4 v4 = ldcs4(src + 4);
    float4 v5 = ldcs4(src + 5);
    float4 v6 = ldcs4(src + 6);
    float4 v7 = ldcs4(src + 7);

    float a[T_STEPS] = { v0.x,v0.y,v0.z,v0.w, v1.x,v1.y,v1.z,v1.w,
                         v2.x,v2.y,v2.z,v2.w, v3.x,v3.y,v3.z,v3.w };
    float b[T_STEPS] = { v4.x,v4.y,v4.z,v4.w, v5.x,v5.y,v5.z,v5.w,
                         v6.x,v6.y,v6.z,v6.w, v7.x,v7.y,v7.z,v7.w };

    lif16(a);
    lif16(b);

    float4* dst = o4 + (size_t)t * 8;
    stcs4(dst + 0, make_float4(a[0],  a[1],  a[2],  a[3]));
    stcs4(dst + 1, make_float4(a[4],  a[5],  a[6],  a[7]));
    stcs4(dst + 2, make_float4(a[8],  a[9],  a[10], a[11]));
    stcs4(dst + 3, make_float4(a[12], a[13], a[14], a[15]));
    stcs4(dst + 4, make_float4(b[0],  b[1],  b[2],  b[3]));
    stcs4(dst + 5, make_float4(b[4],  b[5],  b[6],  b[7]));
    stcs4(dst + 6, make_float4(b[8],  b[9],  b[10], b[11]));
    stcs4(dst + 7, make_float4(b[12], b[13], b[14], b[15]));
}

extern "C" void kernel_launch(void* const* d_in, const int* in_sizes, int n_in,
                              void* d_out, int out_size) {
    const float4* x4 = (const float4*)d_in[0];
    float4* o4 = (float4*)d_out;
    int n_total = in_sizes[0];                  // 67108864
    int n_pairs = n_total / (2 * T_STEPS);      // 2097152
    int threads = 256;
    int blocks = (n_pairs + threads - 1) / threads;
    lif_kernel<<<blocks, threads>>>(x4, o4, n_pairs);
}

// round 3
// speedup vs baseline: 1.7005x; 1.7005x over previous
#include <cuda_runtime.h>

// LIF scan: X[B,C,H,W,T=16] fp32 -> spikes same shape.
// mem = mem*0.5 + x_t; s = (mem >= 1); mem = s ? 0 : mem
//
// Strategy: R1 was L1-wavefront-bound (64B/lane stride -> 16 lines per LDG.128).
// Here all global traffic is perfectly coalesced (16B/lane, 4 lines per LDG.128)
// and the neuron-major <-> time-major transpose happens in shared memory with an
// XOR swizzle that is bank-conflict-free in both access phases.

#define DECAY  0.5f
#define THRESH 1.0f
#define T_STEPS 16
#define THREADS 256
#define F4_PER_BLOCK (THREADS * 4)   // 256 neurons * 4 float4 = 1024

// Swizzled float4 slot for (neuron n in block, logical quarter j)
__device__ __forceinline__ int slot(int n, int j) {
    return n * 4 + (j ^ ((n ^ (n >> 2)) & 3));
}

__global__ void __launch_bounds__(THREADS)
lif_kernel(const float4* __restrict__ x4, float4* __restrict__ o4) {
    __shared__ float4 sm[F4_PER_BLOCK];

    const int tid = threadIdx.x;
    const size_t base = (size_t)blockIdx.x * F4_PER_BLOCK;

    // ---- Stage in: 4 fully-coalesced LDG.128, swizzled STS ----
#pragma unroll
    for (int i = 0; i < 4; i++) {
        float4 v = x4[base + i * THREADS + tid];
        int x = i * THREADS + tid;
        int n = x >> 2, j = x & 3;
        sm[slot(n, j)] = v;
    }
    __syncthreads();

    // ---- Gather this thread's neuron (16 floats) — conflict-free LDS.128 ----
    const int n   = tid;
    const int swz = (n ^ (n >> 2)) & 3;
    float4 q0 = sm[n * 4 + (0 ^ swz)];
    float4 q1 = sm[n * 4 + (1 ^ swz)];
    float4 q2 = sm[n * 4 + (2 ^ swz)];
    float4 q3 = sm[n * 4 + (3 ^ swz)];

    float f[T_STEPS] = { q0.x,q0.y,q0.z,q0.w, q1.x,q1.y,q1.z,q1.w,
                         q2.x,q2.y,q2.z,q2.w, q3.x,q3.y,q3.z,q3.w };

    float mem = 0.0f;
#pragma unroll
    for (int i = 0; i < T_STEPS; i++) {
        mem = fmaf(mem, DECAY, f[i]);
        bool fire = (mem >= THRESH);
        f[i] = fire ? 1.0f : 0.0f;
        mem  = fire ? 0.0f : mem;
    }

    // ---- Scatter back through smem (conflict-free STS.128) ----
    __syncthreads();   // everyone finished reading input staging
    sm[n * 4 + (0 ^ swz)] = make_float4(f[0],  f[1],  f[2],  f[3]);
    sm[n * 4 + (1 ^ swz)] = make_float4(f[4],  f[5],  f[6],  f[7]);
    sm[n * 4 + (2 ^ swz)] = make_float4(f[8],  f[9],  f[10], f[11]);
    sm[n * 4 + (3 ^ swz)] = make_float4(f[12], f[13], f[14], f[15]);
    __syncthreads();

    // ---- Stage out: swizzled LDS, 4 fully-coalesced STG.128 ----
#pragma unroll
    for (int i = 0; i < 4; i++) {
        int x = i * THREADS + tid;
        int nn = x >> 2, j = x & 3;
        o4[base + x] = sm[slot(nn, j)];
    }
}

extern "C" void kernel_launch(void* const* d_in, const int* in_sizes, int n_in,
                              void* d_out, int out_size) {
    const float4* x4 = (const float4*)d_in[0];
    float4* o4 = (float4*)d_out;
    int n_total = in_sizes[0];                   // 67108864 floats
    int n_neurons = n_total / T_STEPS;           // 4194304
    int blocks = n_neurons / THREADS;            // 16384
    lif_kernel<<<blocks, THREADS>>>(x4, o4);
}